// round 16
// baseline (speedup 1.0000x reference)
#include <cuda_runtime.h>
#include <cuda_bf16.h>
#include <cuda_fp16.h>
#include <cstdint>

// Problem constants (fixed by the dataset)
#define DHEAD 128
#define MPROJ 128
#define NQ    4096
#define NK    8192
#define SCALE_CONST 0.009791516698f  // sqrt(pi/2)/128

// ---------------- device-global scratch (pre-swizzled SW128 slab layout) -------
// g_q / g_signs: fp16, 128-row tiles of 32KB; two 16KB slabs (64 cols each);
//                slab offset = sw128(row*128 + col*2).
__device__ __half g_signs[NK * MPROJ];
__device__ float  g_nscale[NK];
__device__ __half g_q[NQ * MPROJ];

__device__ __forceinline__ uint32_t sw128(uint32_t x) { return x ^ ((x >> 3) & 0x70); }

// ================================================================================
// Prep — BALANCED PERSISTENT (one clean wave of 592 blocks = 4/SM x 148).
// Block owns one S column-half (64 projection rows), smem-resident across its
// unit range. Units = 16 input rows. 768 units per half, ~2.6 units/block.
// fp32 FMA, k ascending per element (bit-identical sign decisions).
//   blocks [0,296):   column half 0
//   blocks [296,592): column half 1
//   units  [0,512):   residual rows (signs + nscale)
//   units  [512,768): query rows (q_proj)
// ================================================================================
#define PU_ROWS 16
#define PREP_THREADS 128
#define NPREP_HALF 296
#define NUNITS 768
#define PADP 132
#define PREP_SMEM_BYTES ((64 * PADP + PU_ROWS * PADP) * 4)   // 42.2 KB

__global__ __launch_bounds__(PREP_THREADS)
void qjl_prep_kernel(const float* __restrict__ query,
                     const float* __restrict__ residual,
                     const float* __restrict__ S)
{
    extern __shared__ float smf[];
    float* Ssh = smf;                       // [64][132]  S half (resident)
    float* Ash = smf + 64 * PADP;           // [16][132]  per-unit rows

    const int tid = threadIdx.x;
    const int half = (blockIdx.x >= NPREP_HALF) ? 1 : 0;
    const int idx  = blockIdx.x - half * NPREP_HALF;
    const int colbase = half * 64;

    // ---- load S column-half once (64 rows x 128 k) ----
    const float4* gS = (const float4*)(S + (size_t)colbase * DHEAD);
    #pragma unroll
    for (int i = tid; i < 64 * 32; i += PREP_THREADS) {
        int r = i >> 5, c4 = i & 31;
        *(float4*)(Ssh + r * PADP + c4 * 4) = gS[i];
    }

    const int u0 = (idx * NUNITS) / NPREP_HALF;
    const int u1 = ((idx + 1) * NUNITS) / NPREP_HALF;

    const int rg = tid & 7;    // 2 rows: 2rg, 2rg+1 (of 16)
    const int cg = tid >> 3;   // 4 cols: 4cg..4cg+3 (of 64)

    for (int u = u0; u < u1; u++) {
        const bool is_res = (u < 512);
        const int rbase = is_res ? u * PU_ROWS : (u - 512) * PU_ROWS;
        const float* src = is_res ? residual : query;

        __syncthreads();   // previous unit's A fully consumed
        const float4* gA = (const float4*)(src + (size_t)rbase * DHEAD);
        #pragma unroll
        for (int i = tid; i < PU_ROWS * 32; i += PREP_THREADS) {
            int r = i >> 5, c4 = i & 31;
            *(float4*)(Ash + r * PADP + c4 * 4) = gA[i];
        }
        __syncthreads();

        // norms: once per row (column-half 0 only); serial k-ascending
        if (is_res && half == 0 && tid < PU_ROWS) {
            float s = 0.f;
            #pragma unroll
            for (int k4 = 0; k4 < 32; k4++) {
                float4 a = *(const float4*)(Ash + tid * PADP + k4 * 4);
                s += a.x * a.x + a.y * a.y + a.z * a.z + a.w * a.w;
            }
            g_nscale[rbase + tid] = sqrtf(s) * SCALE_CONST;
        }

        float acc[2][4];
        #pragma unroll
        for (int i = 0; i < 2; i++)
            #pragma unroll
            for (int j = 0; j < 4; j++) acc[i][j] = 0.f;

        const float* arow0 = Ash + (2 * rg) * PADP;
        const float* arow1 = arow0 + PADP;
        const float* brows = Ssh + (4 * cg) * PADP;

        #pragma unroll 8
        for (int k4 = 0; k4 < 32; k4++) {
            float4 a0 = *(const float4*)(arow0 + k4 * 4);
            float4 a1 = *(const float4*)(arow1 + k4 * 4);
            #pragma unroll
            for (int j = 0; j < 4; j++) {
                float4 b = *(const float4*)(brows + j * PADP + k4 * 4);
                acc[0][j] = fmaf(a0.x, b.x, acc[0][j]);
                acc[0][j] = fmaf(a0.y, b.y, acc[0][j]);
                acc[0][j] = fmaf(a0.z, b.z, acc[0][j]);
                acc[0][j] = fmaf(a0.w, b.w, acc[0][j]);
                acc[1][j] = fmaf(a1.x, b.x, acc[1][j]);
                acc[1][j] = fmaf(a1.y, b.y, acc[1][j]);
                acc[1][j] = fmaf(a1.z, b.z, acc[1][j]);
                acc[1][j] = fmaf(a1.w, b.w, acc[1][j]);
            }
        }

        const int col4 = colbase + 4 * cg;   // global col base (8B-aligned store)
        if (is_res) {
            #pragma unroll
            for (int i = 0; i < 2; i++) {
                union { __half h[4]; uint2 u2; } pk;
                #pragma unroll
                for (int j = 0; j < 4; j++)
                    pk.h[j] = __float2half(acc[i][j] >= 0.f ? 1.f : -1.f);
                int row = rbase + 2 * rg + i;
                uint32_t off = (uint32_t)(row >> 7) * 32768u
                             + (uint32_t)(col4 >> 6) * 16384u
                             + sw128((uint32_t)(row & 127) * 128u + (uint32_t)(col4 & 63) * 2u);
                *(uint2*)((char*)g_signs + off) = pk.u2;
            }
        } else {
            #pragma unroll
            for (int i = 0; i < 2; i++) {
                union { __half h[4]; uint2 u2; } ph;
                #pragma unroll
                for (int j = 0; j < 4; j++)
                    ph.h[j] = __float2half(acc[i][j]);
                int row = rbase + 2 * rg + i;
                uint32_t off = (uint32_t)(row >> 7) * 32768u
                             + (uint32_t)(col4 >> 6) * 16384u
                             + sw128((uint32_t)(row & 127) * 128u + (uint32_t)(col4 & 63) * 2u);
                *(uint2*)((char*)g_q + off) = ph.u2;
            }
        }
    }
}

// ================================================================================
// Main GEMM via mma.sync fp16 — BALANCED PERSISTENT PARTITION (R15 exact,
// 38.9us measured). Grid = 296 CTAs (2/SM x 148). 4096 units (64 q x 64 k,
// q-major) in contiguous ranges. A fragments register-resident per q.
// B + nscale double-buffered cp.async. 8 warps, warp tile 32x32, SW128 smem.
// Coalesced staged epilogue.
// ================================================================================
#define NCTA 296
#define UTOT 4096                   // 64 q x 64 k units
#define MT3 256
#define SA    0                     // 16 KB A (two 8KB half-slabs)
#define SB    16384                 // 2 x 32 KB B
#define SNSC  81920                 // 2 x 512 B nscale
#define SST   (SNSC + 1024)         // 8 x 2304 B per-warp staging
#define STPITCH 144
#define MAIN_SMEM_BYTES (SST + 8 * 16 * STPITCH)

__device__ __forceinline__ void ldm_x4(uint32_t* r, uint32_t addr) {
    asm volatile("ldmatrix.sync.aligned.m8n8.x4.shared.b16 {%0,%1,%2,%3}, [%4];"
                 : "=r"(r[0]), "=r"(r[1]), "=r"(r[2]), "=r"(r[3])
                 : "r"(addr));
}

__device__ __forceinline__ void mma_fp16(float* d, const uint32_t* a,
                                         uint32_t b0, uint32_t b1) {
    asm volatile(
        "mma.sync.aligned.m16n8k16.row.col.f32.f16.f16.f32 "
        "{%0,%1,%2,%3}, {%4,%5,%6,%7}, {%8,%9}, {%0,%1,%2,%3};"
        : "+f"(d[0]), "+f"(d[1]), "+f"(d[2]), "+f"(d[3])
        : "r"(a[0]), "r"(a[1]), "r"(a[2]), "r"(a[3]), "r"(b0), "r"(b1));
}

__device__ __forceinline__ void cpa16(uint32_t s, const void* g) {
    asm volatile("cp.async.cg.shared.global [%0], [%1], 16;" :: "r"(s), "l"(g));
}
__device__ __forceinline__ void cpa_commit() {
    asm volatile("cp.async.commit_group;");
}

__global__ __launch_bounds__(MT3, 2)
void qjl_mma5_kernel(float* __restrict__ out)
{
    extern __shared__ char smem[];
    uint32_t sb;
    asm("{ .reg .u64 t; cvta.to.shared.u64 t, %1; cvt.u32.u64 %0, t; }"
        : "=r"(sb) : "l"(smem));

    const int tid = threadIdx.x;
    const int warp = tid >> 5, lane = tid & 31;
    const int cid = blockIdx.x;
    const int base = (cid * UTOT) / NCTA;
    const int end  = ((cid + 1) * UTOT) / NCTA;

    const int wm = warp >> 2;          // 0..1  (q 32-half)
    const int wn = warp & 3;           // 0..3  (k 32-quarter)
    const int lr = lane & 15;
    const uint32_t lcB = (uint32_t)(lane >> 4) * 16u;

    // ---- prologue: A(q of base) [group], then B(base)+nsc [group] ----
    int qcur = base >> 6;
    {
        const char* gAbase = (const char*)g_q + (size_t)(qcur >> 1) * 32768
                           + (uint32_t)(qcur & 1) * 8192u;
        #pragma unroll
        for (int i = tid; i < 1024; i += MT3) {
            int s = i >> 9, d = (i & 511) * 16;
            cpa16(sb + SA + s * 8192 + d, gAbase + s * 16384 + d);
        }
        cpa_commit();
        const int kt = base & 63;
        const char* gB = (const char*)g_signs + (size_t)kt * 32768;
        #pragma unroll
        for (int i = tid; i < 2048; i += MT3)
            cpa16(sb + SB + i * 16, gB + i * 16);
        if (tid < 32)
            cpa16(sb + SNSC + tid * 16, (const char*)(g_nscale + kt * 128) + tid * 16);
        cpa_commit();
    }

    asm volatile("cp.async.wait_group 1;" ::: "memory");
    __syncthreads();

    // ---- A fragments register-resident ----
    uint32_t af[8][2][4];
    {
        const uint32_t arow = (uint32_t)(wm * 32 + lr) * 128u + lcB;
        #pragma unroll
        for (int ks = 0; ks < 8; ks++)
            #pragma unroll
            for (int i = 0; i < 2; i++)
                ldm_x4(af[ks][i],
                       sb + SA + (ks >> 2) * 8192
                          + sw128(arow + (uint32_t)i * 2048u + (uint32_t)(ks & 3) * 32u));
    }

    uint32_t brow[2];
    brow[0] = (uint32_t)(wn * 32 + lr) * 128u + lcB;
    brow[1] = brow[0] + 2048u;

    char* stg = smem + SST + warp * (16 * STPITCH);
    int qpend = qcur;   // q whose A tile is in smem

    #pragma unroll 1
    for (int i = base; i < end; i++) {
        const int buf = (i - base) & 1;
        const int kt = (i & 63) * 128;

        asm volatile("cp.async.wait_group 0;" ::: "memory");
        __syncthreads();   // B[i] (+A if switched) visible; all warps past buf^1

        if (qpend != qcur) {   // q-boundary: reload A fragments from fresh smem
            qcur = qpend;
            const uint32_t arow = (uint32_t)(wm * 32 + lr) * 128u + lcB;
            #pragma unroll
            for (int ks = 0; ks < 8; ks++)
                #pragma unroll
                for (int ii = 0; ii < 2; ii++)
                    ldm_x4(af[ks][ii],
                           sb + SA + (ks >> 2) * 8192
                              + sw128(arow + (uint32_t)ii * 2048u
                                      + (uint32_t)(ks & 3) * 32u));
        }

        if (i + 1 < end) {   // prefetch unit i+1 (B always; A if q changes)
            const int qn = (i + 1) >> 6;
            if (qn != qpend) {
                qpend = qn;
                const char* gAbase = (const char*)g_q + (size_t)(qn >> 1) * 32768
                                   + (uint32_t)(qn & 1) * 8192u;
                #pragma unroll
                for (int ii = tid; ii < 1024; ii += MT3) {
                    int s = ii >> 9, d = (ii & 511) * 16;
                    cpa16(sb + SA + s * 8192 + d, gAbase + s * 16384 + d);
                }
            }
            const int ktn = (i + 1) & 63;
            const int nb = buf ^ 1;
            const char* gB = (const char*)g_signs + (size_t)ktn * 32768;
            #pragma unroll
            for (int ii = tid; ii < 2048; ii += MT3)
                cpa16(sb + SB + nb * 32768 + ii * 16, gB + ii * 16);
            if (tid < 32)
                cpa16(sb + SNSC + nb * 512 + tid * 16,
                      (const char*)(g_nscale + ktn * 128) + tid * 16);
            cpa_commit();
        }

        const uint32_t bbase = sb + SB + buf * 32768;
        const float* nscs = (const float*)(smem + SNSC + buf * 512);

        float acc[2][4][4];
        #pragma unroll
        for (int ii = 0; ii < 2; ii++)
            #pragma unroll
            for (int j = 0; j < 4; j++)
                #pragma unroll
                for (int t = 0; t < 4; t++) acc[ii][j][t] = 0.f;

        #pragma unroll
        for (int ks = 0; ks < 8; ks++) {
            uint32_t bf[2][4];
            #pragma unroll
            for (int jj = 0; jj < 2; jj++)
                ldm_x4(bf[jj], bbase + (ks >> 2) * 16384
                             + sw128(brow[jj] + (uint32_t)(ks & 3) * 32u));
            #pragma unroll
            for (int ii = 0; ii < 2; ii++)
                #pragma unroll
                for (int n8 = 0; n8 < 4; n8++)
                    mma_fp16(acc[ii][n8], af[ks][ii],
                             bf[n8 >> 1][n8 & 1], bf[n8 >> 1][(n8 & 1) + 2]);
        }

        // ---- coalesced epilogue: stage 16-row halves, store 128B lines ----
        const int qtile = qcur * 64;
        const int rr = lane >> 2;
        const int cbase = 2 * (lane & 3);
        #pragma unroll
        for (int ii = 0; ii < 2; ii++) {
            #pragma unroll
            for (int n8 = 0; n8 < 4; n8++) {
                int cl = wn * 32 + cbase + n8 * 8;
                float s0 = nscs[cl], s1 = nscs[cl + 1];
                int scol = cbase + n8 * 8;
                *(float2*)(stg + rr * STPITCH + scol * 4) =
                    make_float2(acc[ii][n8][0] * s0, acc[ii][n8][1] * s1);
                *(float2*)(stg + (rr + 8) * STPITCH + scol * 4) =
                    make_float2(acc[ii][n8][2] * s0, acc[ii][n8][3] * s1);
            }
            __syncwarp();
            const int lrow = lane >> 3;
            const int lcol = (lane & 7) * 4;
            #pragma unroll
            for (int p = 0; p < 4; p++) {
                int row = lrow + p * 4;
                float4 v = *(const float4*)(stg + row * STPITCH + lcol * 4);
                int grow = qtile + wm * 32 + ii * 16 + row;
                int gcol = kt + wn * 32 + lcol;
                *(float4*)(out + (size_t)grow * NK + gcol) = v;
            }
            __syncwarp();
        }
    }
}

// ================================================================================
extern "C" void kernel_launch(void* const* d_in, const int* in_sizes, int n_in,
                              void* d_out, int out_size)
{
    const float* query    = (const float*)d_in[0];
    const float* residual = (const float*)d_in[1];
    const float* S        = (const float*)d_in[2];
    float* out = (float*)d_out;

    cudaFuncSetAttribute(qjl_prep_kernel,
                         cudaFuncAttributeMaxDynamicSharedMemorySize, PREP_SMEM_BYTES);
    cudaFuncSetAttribute(qjl_mma5_kernel,
                         cudaFuncAttributeMaxDynamicSharedMemorySize, MAIN_SMEM_BYTES);

    // balanced persistent prep: one clean wave of 592 blocks (4/SM x 148)
    qjl_prep_kernel<<<2 * NPREP_HALF, PREP_THREADS, PREP_SMEM_BYTES>>>(
        query, residual, S);

    // balanced persistent main: one clean wave of 296 CTAs
    qjl_mma5_kernel<<<NCTA, MT3, MAIN_SMEM_BYTES>>>(out);
}